// round 7
// baseline (speedup 1.0000x reference)
#include <cuda_runtime.h>
#include <cuda_fp16.h>
#include <math.h>
#include <stdint.h>

// ---------------- Problem constants ----------------
#define Bb 8
#define Tt 8192
#define Cc 512
#define Hh 8
#define Dd 64
#define NN (Bb*Tt)         // 65536 tokens
#define BH (Bb*Hh)         // 64
#define KV_SPLIT 8

// ---------------- Scratch (device globals) ----------------
__device__ __half g_Xh[(size_t)NN*Cc];
__device__ __half g_Wh[(size_t)4*Cc*Cc];
__device__ __half g_Qh[(size_t)NN*Cc];
__device__ __half g_Kh[(size_t)NN*Cc];
__device__ __half g_Vh[(size_t)NN*Cc];
__device__ __half g_Yh[(size_t)NN*Cc];
__device__ float  g_KV[(size_t)BH*Dd*Dd];
__device__ float  g_Ksum[(size_t)BH*Dd];

// ---------------- helpers ----------------
__device__ __forceinline__ uint32_t smem_u32(const void* p) {
    uint32_t a;
    asm("{ .reg .u64 t; cvta.to.shared.u64 t, %1; cvt.u32.u64 %0, t; }" : "=r"(a) : "l"(p));
    return a;
}
#define CP_ASYNC16(dst, src) \
    asm volatile("cp.async.cg.shared.global [%0], [%1], 16;" :: "r"(dst), "l"(src) : "memory")
#define CP_COMMIT() asm volatile("cp.async.commit_group;" ::: "memory")
#define CP_WAIT(n)  asm volatile("cp.async.wait_group %0;" :: "n"(n) : "memory")

__device__ __forceinline__ void ldsm_x4(uint32_t* r, uint32_t addr) {
    asm volatile("ldmatrix.sync.aligned.m8n8.x4.shared.b16 {%0,%1,%2,%3}, [%4];"
                 : "=r"(r[0]), "=r"(r[1]), "=r"(r[2]), "=r"(r[3]) : "r"(addr));
}
__device__ __forceinline__ void mma_f16(float* c, const uint32_t* a, uint32_t b0, uint32_t b1) {
    asm volatile("mma.sync.aligned.m16n8k16.row.col.f32.f16.f16.f32 "
                 "{%0,%1,%2,%3},{%4,%5,%6,%7},{%8,%9},{%0,%1,%2,%3};"
                 : "+f"(c[0]), "+f"(c[1]), "+f"(c[2]), "+f"(c[3])
                 : "r"(a[0]), "r"(a[1]), "r"(a[2]), "r"(a[3]), "r"(b0), "r"(b1));
}

// ---------------- GEMM config (fp16, 128x256 CTA, 64x64 warp) ----------------
#define BM 128
#define BN 256
#define BKH 64                      // K halves per stage (128 B rows)
#define NKH (Cc / BKH)              // 8
#define ASTRH 72                    // padded row stride in halves
#define A_TILEH (BM * ASTRH)        // 9216
#define B_TILEH (BN * ASTRH)        // 18432
#define STAGEH (A_TILEH + B_TILEH)  // 27648 halves
#define NSTG 3
#define GEMM_SMEM (NSTG * STAGEH * 2)   // 165888 bytes

// out[m, n] = sum_k A[m,k]*B[n,k] + bias[n]; act -> elu(v)+1; outHalf -> fp16 store
__global__ __launch_bounds__(256)
void gemm_f16(const __half* __restrict__ A, const __half* __restrict__ B,
              const float* __restrict__ bias, void* __restrict__ outp,
              int act, int outHalf)
{
    extern __shared__ __half smh[];
    const int tid = threadIdx.x;
    const int wid = tid >> 5;
    const int lane = tid & 31;
    const int m0 = blockIdx.x * BM;
    const int n0 = blockIdx.y * BN;

    const int m_warp = (wid >> 2) * 64;     // 0 / 64
    const int n_warp = (wid & 3) * 64;      // 0 / 64 / 128 / 192

    // ldmatrix x4 addressing (thread group g8 = lane/8 picks matrix)
    const int g8 = lane >> 3;
    const int r8 = lane & 7;
    const int a_row_l = r8 + (g8 & 1) * 8;
    const int a_kb    = (g8 >> 1) * 16;
    const int b_row_l = r8 + (g8 >> 1) * 8;
    const int b_kb    = (g8 & 1) * 16;

    const uint32_t smb = smem_u32(smh);

    float acc[4][8][4];
#pragma unroll
    for (int i = 0; i < 4; i++)
#pragma unroll
        for (int j = 0; j < 8; j++)
#pragma unroll
            for (int k = 0; k < 4; k++) acc[i][j][k] = 0.f;

    auto load_stage = [&](int kc, int s) {
        const __half* gA = A + (size_t)m0 * Cc + kc * BKH;
        const __half* gB = B + (size_t)n0 * Cc + kc * BKH;
        uint32_t dA = smb + (uint32_t)(s * STAGEH) * 2;
        uint32_t dB = dA + (uint32_t)A_TILEH * 2;
#pragma unroll
        for (int i = 0; i < 4; i++) {            // A: 1024 16B units
            int idx = tid + i * 256;
            int row = idx >> 3;
            int c8 = idx & 7;
            CP_ASYNC16(dA + (uint32_t)(row * ASTRH + c8 * 8) * 2, gA + (size_t)row * Cc + c8 * 8);
        }
#pragma unroll
        for (int i = 0; i < 8; i++) {            // B: 2048 16B units
            int idx = tid + i * 256;
            int row = idx >> 3;
            int c8 = idx & 7;
            CP_ASYNC16(dB + (uint32_t)(row * ASTRH + c8 * 8) * 2, gB + (size_t)row * Cc + c8 * 8);
        }
        CP_COMMIT();
    };

    load_stage(0, 0);
    load_stage(1, 1);

    for (int kt = 0; kt < NKH; kt++) {
        if (kt < NKH - 1) CP_WAIT(1); else CP_WAIT(0);
        __syncthreads();                         // also guards WAR on stage (kt+2)%3
        if (kt + 2 < NKH) load_stage(kt + 2, (kt + 2) % 3);

        const int s = kt % 3;
        const uint32_t aB = smb + (uint32_t)(s * STAGEH) * 2
                          + (uint32_t)((m_warp + a_row_l) * ASTRH) * 2 + a_kb;
        const uint32_t bB = smb + (uint32_t)(s * STAGEH + A_TILEH) * 2
                          + (uint32_t)((n_warp + b_row_l) * ASTRH) * 2 + b_kb;

#pragma unroll
        for (int ks = 0; ks < 4; ks++) {         // 4 x k16 = 64
            uint32_t af[4][4];
#pragma unroll
            for (int mi = 0; mi < 4; mi++)
                ldsm_x4(af[mi], aB + (uint32_t)(mi * 16 * ASTRH) * 2 + ks * 32);
            uint32_t bf[4][4];
#pragma unroll
            for (int p = 0; p < 4; p++)
                ldsm_x4(bf[p], bB + (uint32_t)(p * 16 * ASTRH) * 2 + ks * 32);
#pragma unroll
            for (int mi = 0; mi < 4; mi++) {
#pragma unroll
                for (int p = 0; p < 4; p++) {
                    mma_f16(acc[mi][p * 2 + 0], af[mi], bf[p][0], bf[p][1]);
                    mma_f16(acc[mi][p * 2 + 1], af[mi], bf[p][2], bf[p][3]);
                }
            }
        }
    }

    // ---- epilogue: bias + optional ELU+1, f32 or f16 store ----
    const int r_lo = lane >> 2;
    const int c_off = (lane & 3) * 2;
#pragma unroll
    for (int mi = 0; mi < 4; mi++) {
#pragma unroll
        for (int nj = 0; nj < 8; nj++) {
            int col = n0 + n_warp + nj * 8 + c_off;
            float b0 = bias[col], b1 = bias[col + 1];
#pragma unroll
            for (int half_ = 0; half_ < 2; half_++) {
                int row = m0 + m_warp + mi * 16 + r_lo + half_ * 8;
                float v0 = acc[mi][nj][half_ * 2 + 0] + b0;
                float v1 = acc[mi][nj][half_ * 2 + 1] + b1;
                if (act) {
                    v0 = (v0 > 0.f) ? v0 + 1.f : expf(v0);
                    v1 = (v1 > 0.f) ? v1 + 1.f : expf(v1);
                }
                if (outHalf) {
                    __half2 hv = __floats2half2_rn(v0, v1);
                    *(__half2*)((__half*)outp + (size_t)row * Cc + col) = hv;
                } else {
                    *(float2*)((float*)outp + (size_t)row * Cc + col) = make_float2(v0, v1);
                }
            }
        }
    }
}

// ---------------- f32 -> f16 conversion ----------------
__global__ __launch_bounds__(256) void cvt_f16(const float4* __restrict__ src,
                                               uint4* __restrict__ dst, int n8)
{
    int i = blockIdx.x * blockDim.x + threadIdx.x;
    if (i < n8) {
        float4 a = src[2 * i], b = src[2 * i + 1];
        __half2 h0 = __floats2half2_rn(a.x, a.y);
        __half2 h1 = __floats2half2_rn(a.z, a.w);
        __half2 h2 = __floats2half2_rn(b.x, b.y);
        __half2 h3 = __floats2half2_rn(b.z, b.w);
        uint4 o;
        o.x = *(uint32_t*)&h0; o.y = *(uint32_t*)&h1;
        o.z = *(uint32_t*)&h2; o.w = *(uint32_t*)&h3;
        dst[i] = o;
    }
}

// ---------------- attention-side kernels ----------------
__global__ void zero_kv()
{
    int i = blockIdx.x * blockDim.x + threadIdx.x;
    if (i < BH * Dd * Dd) g_KV[i] = 0.f;
    if (i < BH * Dd)      g_Ksum[i] = 0.f;
}

__global__ __launch_bounds__(256) void kv_accum()
{
    const int bh = blockIdx.x;
    const int b = bh >> 3, h = bh & 7;
    const int tid = threadIdx.x;
    const int rows = Tt / KV_SPLIT;
    const size_t base = ((size_t)b * Tt + (size_t)blockIdx.y * rows) * Cc + h * Dd;

    __shared__ float sK[8][64];
    __shared__ float sV[8][64];

    const int d0 = (tid >> 4) * 4;
    const int e0 = (tid & 15) * 4;

    const int ld_r = tid >> 5;           // 0..7
    const int ld_p = (tid & 31) * 2;     // 0,2,..,62

    float acc[4][4];
#pragma unroll
    for (int i = 0; i < 4; i++)
#pragma unroll
        for (int j = 0; j < 4; j++) acc[i][j] = 0.f;
    float ks = 0.f;

    for (int r0 = 0; r0 < rows; r0 += 8) {
        {
            size_t g = base + (size_t)(r0 + ld_r) * Cc + ld_p;
            float2 kf = __half22float2(*(const __half2*)(g_Kh + g));
            float2 vf = __half22float2(*(const __half2*)(g_Vh + g));
            sK[ld_r][ld_p] = kf.x; sK[ld_r][ld_p + 1] = kf.y;
            sV[ld_r][ld_p] = vf.x; sV[ld_r][ld_p + 1] = vf.y;
        }
        __syncthreads();
#pragma unroll
        for (int r = 0; r < 8; r++) {
            float k0 = sK[r][d0], k1 = sK[r][d0 + 1], k2 = sK[r][d0 + 2], k3 = sK[r][d0 + 3];
            float v0 = sV[r][e0], v1 = sV[r][e0 + 1], v2 = sV[r][e0 + 2], v3 = sV[r][e0 + 3];
            acc[0][0] = fmaf(k0, v0, acc[0][0]); acc[0][1] = fmaf(k0, v1, acc[0][1]);
            acc[0][2] = fmaf(k0, v2, acc[0][2]); acc[0][3] = fmaf(k0, v3, acc[0][3]);
            acc[1][0] = fmaf(k1, v0, acc[1][0]); acc[1][1] = fmaf(k1, v1, acc[1][1]);
            acc[1][2] = fmaf(k1, v2, acc[1][2]); acc[1][3] = fmaf(k1, v3, acc[1][3]);
            acc[2][0] = fmaf(k2, v0, acc[2][0]); acc[2][1] = fmaf(k2, v1, acc[2][1]);
            acc[2][2] = fmaf(k2, v2, acc[2][2]); acc[2][3] = fmaf(k2, v3, acc[2][3]);
            acc[3][0] = fmaf(k3, v0, acc[3][0]); acc[3][1] = fmaf(k3, v1, acc[3][1]);
            acc[3][2] = fmaf(k3, v2, acc[3][2]); acc[3][3] = fmaf(k3, v3, acc[3][3]);
        }
        if (tid < 64) {
#pragma unroll
            for (int r = 0; r < 8; r++) ks += sK[r][tid];
        }
        __syncthreads();
    }

    float* kvp = g_KV + (size_t)bh * Dd * Dd;
#pragma unroll
    for (int i = 0; i < 4; i++)
#pragma unroll
        for (int j = 0; j < 4; j++)
            atomicAdd(&kvp[(d0 + i) * Dd + (e0 + j)], acc[i][j]);
    if (tid < 64) atomicAdd(&g_Ksum[bh * Dd + tid], ks);
}

__global__ __launch_bounds__(256) void y_kernel()
{
    const int bh = blockIdx.y;
    const int b = bh >> 3, h = bh & 7;
    const int t0 = blockIdx.x * 64;
    const int tid = threadIdx.x;

    __shared__ float sKV[64][64];
    __shared__ float sQ[64][65];
    __shared__ float sks[64];

    const float* kvp = g_KV + (size_t)bh * Dd * Dd;
#pragma unroll
    for (int i = 0; i < 16; i++) {
        int idx = tid + i * 256;
        sKV[idx >> 6][idx & 63] = kvp[idx];
    }
    if (tid < 64) sks[tid] = g_Ksum[bh * Dd + tid];
#pragma unroll
    for (int i = 0; i < 8; i++) {
        int idx = tid + i * 256;                 // 0..2047 half2 slots (64 rows x 32)
        int r = idx >> 5;
        int d2 = (idx & 31) * 2;
        float2 qf = __half22float2(*(const __half2*)(
            g_Qh + ((size_t)b * Tt + t0 + r) * Cc + h * Dd + d2));
        sQ[r][d2] = qf.x; sQ[r][d2 + 1] = qf.y;
    }
    __syncthreads();

    const int tok = tid >> 2;
    const int e0 = (tid & 3) * 16;

    float acc[16];
#pragma unroll
    for (int j = 0; j < 16; j++) acc[j] = 0.f;
    float nrm = 0.f;

#pragma unroll
    for (int d = 0; d < 64; d++) {
        float q = sQ[tok][d];
        nrm = fmaf(q, sks[d], nrm);
        const float4* kr = (const float4*)&sKV[d][e0];
        float4 c0 = kr[0], c1 = kr[1], c2 = kr[2], c3 = kr[3];
        acc[0]  = fmaf(q, c0.x, acc[0]);  acc[1]  = fmaf(q, c0.y, acc[1]);
        acc[2]  = fmaf(q, c0.z, acc[2]);  acc[3]  = fmaf(q, c0.w, acc[3]);
        acc[4]  = fmaf(q, c1.x, acc[4]);  acc[5]  = fmaf(q, c1.y, acc[5]);
        acc[6]  = fmaf(q, c1.z, acc[6]);  acc[7]  = fmaf(q, c1.w, acc[7]);
        acc[8]  = fmaf(q, c2.x, acc[8]);  acc[9]  = fmaf(q, c2.y, acc[9]);
        acc[10] = fmaf(q, c2.z, acc[10]); acc[11] = fmaf(q, c2.w, acc[11]);
        acc[12] = fmaf(q, c3.x, acc[12]); acc[13] = fmaf(q, c3.y, acc[13]);
        acc[14] = fmaf(q, c3.z, acc[14]); acc[15] = fmaf(q, c3.w, acc[15]);
    }

    float inv = 1.f / (nrm + 1e-6f);
    size_t ob = ((size_t)b * Tt + t0 + tok) * Cc + h * Dd + e0;
#pragma unroll
    for (int j = 0; j < 16; j += 2) {
        __half2 hv = __floats2half2_rn(acc[j] * inv, acc[j + 1] * inv);
        *(__half2*)(g_Yh + ob + j) = hv;
    }
}

// ---------------- launch ----------------
extern "C" void kernel_launch(void* const* d_in, const int* in_sizes, int n_in,
                              void* d_out, int out_size)
{
    const float* x  = (const float*)d_in[0];
    const float* Wq = (const float*)d_in[1];
    const float* bq = (const float*)d_in[2];
    const float* Wk = (const float*)d_in[3];
    const float* bk = (const float*)d_in[4];
    const float* Wv = (const float*)d_in[5];
    const float* bv = (const float*)d_in[6];
    const float* Wo = (const float*)d_in[7];
    const float* bo = (const float*)d_in[8];
    float* out = (float*)d_out;

    static __half *pXh = nullptr, *pWh, *pQh, *pKh, *pVh, *pYh;
    static bool inited = false;
    if (!inited) {
        cudaGetSymbolAddress((void**)&pXh, g_Xh);
        cudaGetSymbolAddress((void**)&pWh, g_Wh);
        cudaGetSymbolAddress((void**)&pQh, g_Qh);
        cudaGetSymbolAddress((void**)&pKh, g_Kh);
        cudaGetSymbolAddress((void**)&pVh, g_Vh);
        cudaGetSymbolAddress((void**)&pYh, g_Yh);
        cudaFuncSetAttribute(gemm_f16, cudaFuncAttributeMaxDynamicSharedMemorySize, GEMM_SMEM);
        inited = true;
    }

    // f32 -> f16 conversion of GEMM inputs
    const float* Ws[4] = {Wq, Wk, Wv, Wo};
    {
        int n8 = NN * Cc / 8;
        cvt_f16<<<n8 / 256, 256>>>((const float4*)x, (uint4*)pXh, n8);
        int w8 = Cc * Cc / 8;
        for (int i = 0; i < 4; i++)
            cvt_f16<<<w8 / 256, 256>>>((const float4*)Ws[i], (uint4*)(pWh + (size_t)i * Cc * Cc), w8);
    }

    dim3 gg(NN / BM, Cc / BN);   // (512, 2)

    gemm_f16<<<gg, 256, GEMM_SMEM>>>(pXh, pWh + 0 * (size_t)Cc * Cc, bq, pQh, 1, 1);
    gemm_f16<<<gg, 256, GEMM_SMEM>>>(pXh, pWh + 1 * (size_t)Cc * Cc, bk, pKh, 1, 1);
    gemm_f16<<<gg, 256, GEMM_SMEM>>>(pXh, pWh + 2 * (size_t)Cc * Cc, bv, pVh, 0, 1);

    zero_kv<<<(BH * Dd * Dd + 255) / 256, 256>>>();
    kv_accum<<<dim3(BH, KV_SPLIT), 256>>>();
    y_kernel<<<dim3(Tt / 64, BH), 256>>>();

    gemm_f16<<<gg, 256, GEMM_SMEM>>>(pYh, pWh + 3 * (size_t)Cc * Cc, bo, out, 0, 0);
}

// round 8
// speedup vs baseline: 1.0260x; 1.0260x over previous
#include <cuda_runtime.h>
#include <cuda_fp16.h>
#include <math.h>
#include <stdint.h>

// ---------------- Problem constants ----------------
#define Bb 8
#define Tt 8192
#define Cc 512
#define Hh 8
#define Dd 64
#define NN (Bb*Tt)         // 65536 tokens
#define BH (Bb*Hh)         // 64
#define KV_SPLIT 8

// ---------------- Scratch (device globals) ----------------
__device__ __half g_Xh[(size_t)NN*Cc];
__device__ __half g_Wh[(size_t)4*Cc*Cc];
__device__ __half g_Qh[(size_t)NN*Cc];
__device__ __half g_Kh[(size_t)NN*Cc];
__device__ __half g_Vh[(size_t)NN*Cc];
__device__ __half g_Yh[(size_t)NN*Cc];
__device__ float  g_KV[(size_t)BH*Dd*Dd];
__device__ float  g_Ksum[(size_t)BH*Dd];

// ---------------- helpers ----------------
__device__ __forceinline__ uint32_t smem_u32(const void* p) {
    uint32_t a;
    asm("{ .reg .u64 t; cvta.to.shared.u64 t, %1; cvt.u32.u64 %0, t; }" : "=r"(a) : "l"(p));
    return a;
}
#define CP_ASYNC16(dst, src) \
    asm volatile("cp.async.cg.shared.global [%0], [%1], 16;" :: "r"(dst), "l"(src) : "memory")
#define CP_COMMIT() asm volatile("cp.async.commit_group;" ::: "memory")
#define CP_WAIT(n)  asm volatile("cp.async.wait_group %0;" :: "n"(n) : "memory")

__device__ __forceinline__ void ldsm_x4(uint32_t* r, uint32_t addr) {
    asm volatile("ldmatrix.sync.aligned.m8n8.x4.shared.b16 {%0,%1,%2,%3}, [%4];"
                 : "=r"(r[0]), "=r"(r[1]), "=r"(r[2]), "=r"(r[3]) : "r"(addr));
}
__device__ __forceinline__ void mma_f16(float* c, const uint32_t* a, uint32_t b0, uint32_t b1) {
    asm volatile("mma.sync.aligned.m16n8k16.row.col.f32.f16.f16.f32 "
                 "{%0,%1,%2,%3},{%4,%5,%6,%7},{%8,%9},{%0,%1,%2,%3};"
                 : "+f"(c[0]), "+f"(c[1]), "+f"(c[2]), "+f"(c[3])
                 : "r"(a[0]), "r"(a[1]), "r"(a[2]), "r"(a[3]), "r"(b0), "r"(b1));
}

// ---------------- GEMM config (fp16, 128x128 CTA, 4 warps of 64x64) ----------------
#define BM 128
#define BN 128
#define BKH 64                      // K halves per stage (128 B rows)
#define NKH (Cc / BKH)              // 8
#define ASTRH 72                    // padded row stride in halves
#define TILEH (BM * ASTRH)          // 9216 halves / operand
#define STAGEH (2 * TILEH)          // A + B
#define NSTG 3
#define GEMM_SMEM (NSTG * STAGEH * 2)   // 110592 bytes
#define NTHR 128

// out[m, n] = sum_k A[m,k]*B[n,k] + bias[n]; act -> elu(v)+1; outHalf -> fp16 store
__global__ __launch_bounds__(NTHR, 2)
void gemm_f16(const __half* __restrict__ A, const __half* __restrict__ B,
              const float* __restrict__ bias, void* __restrict__ outp,
              int act, int outHalf)
{
    extern __shared__ __half smh[];
    const int tid = threadIdx.x;
    const int wid = tid >> 5;        // 0..3
    const int lane = tid & 31;
    const int m0 = blockIdx.x * BM;
    const int n0 = blockIdx.y * BN;

    const int m_warp = (wid >> 1) * 64;     // 0 / 64
    const int n_warp = (wid & 1) * 64;      // 0 / 64

    // ldmatrix x4 addressing (thread group g8 = lane/8 picks matrix)
    const int g8 = lane >> 3;
    const int r8 = lane & 7;
    const int a_row_l = r8 + (g8 & 1) * 8;
    const int a_kb    = (g8 >> 1) * 16;
    const int b_row_l = r8 + (g8 >> 1) * 8;
    const int b_kb    = (g8 & 1) * 16;

    const uint32_t smb = smem_u32(smh);

    float acc[4][8][4];
#pragma unroll
    for (int i = 0; i < 4; i++)
#pragma unroll
        for (int j = 0; j < 8; j++)
#pragma unroll
            for (int k = 0; k < 4; k++) acc[i][j][k] = 0.f;

    auto load_stage = [&](int kc, int s) {
        const __half* gA = A + (size_t)m0 * Cc + kc * BKH;
        const __half* gB = B + (size_t)n0 * Cc + kc * BKH;
        uint32_t dA = smb + (uint32_t)(s * STAGEH) * 2;
        uint32_t dB = dA + (uint32_t)TILEH * 2;
#pragma unroll
        for (int i = 0; i < 8; i++) {            // A: 1024 16B units / 128 thr
            int idx = tid + i * NTHR;
            int row = idx >> 3;
            int c8 = idx & 7;
            CP_ASYNC16(dA + (uint32_t)(row * ASTRH + c8 * 8) * 2, gA + (size_t)row * Cc + c8 * 8);
        }
#pragma unroll
        for (int i = 0; i < 8; i++) {            // B: 1024 16B units
            int idx = tid + i * NTHR;
            int row = idx >> 3;
            int c8 = idx & 7;
            CP_ASYNC16(dB + (uint32_t)(row * ASTRH + c8 * 8) * 2, gB + (size_t)row * Cc + c8 * 8);
        }
        CP_COMMIT();
    };

    load_stage(0, 0);
    load_stage(1, 1);

    for (int kt = 0; kt < NKH; kt++) {
        if (kt < NKH - 1) CP_WAIT(1); else CP_WAIT(0);
        __syncthreads();                         // also guards WAR on stage (kt+2)%3
        if (kt + 2 < NKH) load_stage(kt + 2, (kt + 2) % 3);

        const int s = kt % 3;
        const uint32_t aB = smb + (uint32_t)(s * STAGEH) * 2
                          + (uint32_t)((m_warp + a_row_l) * ASTRH) * 2 + a_kb;
        const uint32_t bB = smb + (uint32_t)(s * STAGEH + TILEH) * 2
                          + (uint32_t)((n_warp + b_row_l) * ASTRH) * 2 + b_kb;

#pragma unroll
        for (int ks = 0; ks < 4; ks++) {         // 4 x k16 = 64
            uint32_t af[4][4];
#pragma unroll
            for (int mi = 0; mi < 4; mi++)
                ldsm_x4(af[mi], aB + (uint32_t)(mi * 16 * ASTRH) * 2 + ks * 32);
            uint32_t bf[4][4];
#pragma unroll
            for (int p = 0; p < 4; p++)
                ldsm_x4(bf[p], bB + (uint32_t)(p * 16 * ASTRH) * 2 + ks * 32);
#pragma unroll
            for (int mi = 0; mi < 4; mi++) {
#pragma unroll
                for (int p = 0; p < 4; p++) {
                    mma_f16(acc[mi][p * 2 + 0], af[mi], bf[p][0], bf[p][1]);
                    mma_f16(acc[mi][p * 2 + 1], af[mi], bf[p][2], bf[p][3]);
                }
            }
        }
    }

    // ---- epilogue: bias + optional ELU+1, f32 or f16 store ----
    const int r_lo = lane >> 2;
    const int c_off = (lane & 3) * 2;
#pragma unroll
    for (int mi = 0; mi < 4; mi++) {
#pragma unroll
        for (int nj = 0; nj < 8; nj++) {
            int col = n0 + n_warp + nj * 8 + c_off;
            float b0 = bias[col], b1 = bias[col + 1];
#pragma unroll
            for (int half_ = 0; half_ < 2; half_++) {
                int row = m0 + m_warp + mi * 16 + r_lo + half_ * 8;
                float v0 = acc[mi][nj][half_ * 2 + 0] + b0;
                float v1 = acc[mi][nj][half_ * 2 + 1] + b1;
                if (act) {
                    v0 = (v0 > 0.f) ? v0 + 1.f : expf(v0);
                    v1 = (v1 > 0.f) ? v1 + 1.f : expf(v1);
                }
                if (outHalf) {
                    __half2 hv = __floats2half2_rn(v0, v1);
                    *(__half2*)((__half*)outp + (size_t)row * Cc + col) = hv;
                } else {
                    *(float2*)((float*)outp + (size_t)row * Cc + col) = make_float2(v0, v1);
                }
            }
        }
    }
}

// ---------------- f32 -> f16 conversion ----------------
__global__ __launch_bounds__(256) void cvt_f16(const float4* __restrict__ src,
                                               uint4* __restrict__ dst, int n8)
{
    int i = blockIdx.x * blockDim.x + threadIdx.x;
    if (i < n8) {
        float4 a = src[2 * i], b = src[2 * i + 1];
        __half2 h0 = __floats2half2_rn(a.x, a.y);
        __half2 h1 = __floats2half2_rn(a.z, a.w);
        __half2 h2 = __floats2half2_rn(b.x, b.y);
        __half2 h3 = __floats2half2_rn(b.z, b.w);
        uint4 o;
        o.x = *(uint32_t*)&h0; o.y = *(uint32_t*)&h1;
        o.z = *(uint32_t*)&h2; o.w = *(uint32_t*)&h3;
        dst[i] = o;
    }
}

// ---------------- attention-side kernels ----------------
__global__ void zero_kv()
{
    int i = blockIdx.x * blockDim.x + threadIdx.x;
    if (i < BH * Dd * Dd) g_KV[i] = 0.f;
    if (i < BH * Dd)      g_Ksum[i] = 0.f;
}

__global__ __launch_bounds__(256) void kv_accum()
{
    const int bh = blockIdx.x;
    const int b = bh >> 3, h = bh & 7;
    const int tid = threadIdx.x;
    const int rows = Tt / KV_SPLIT;
    const size_t base = ((size_t)b * Tt + (size_t)blockIdx.y * rows) * Cc + h * Dd;

    __shared__ float sK[8][64];
    __shared__ float sV[8][64];

    const int d0 = (tid >> 4) * 4;
    const int e0 = (tid & 15) * 4;

    const int ld_r = tid >> 5;           // 0..7
    const int ld_p = (tid & 31) * 2;     // 0,2,..,62

    float acc[4][4];
#pragma unroll
    for (int i = 0; i < 4; i++)
#pragma unroll
        for (int j = 0; j < 4; j++) acc[i][j] = 0.f;
    float ks = 0.f;

    for (int r0 = 0; r0 < rows; r0 += 8) {
        {
            size_t g = base + (size_t)(r0 + ld_r) * Cc + ld_p;
            float2 kf = __half22float2(*(const __half2*)(g_Kh + g));
            float2 vf = __half22float2(*(const __half2*)(g_Vh + g));
            sK[ld_r][ld_p] = kf.x; sK[ld_r][ld_p + 1] = kf.y;
            sV[ld_r][ld_p] = vf.x; sV[ld_r][ld_p + 1] = vf.y;
        }
        __syncthreads();
#pragma unroll
        for (int r = 0; r < 8; r++) {
            float k0 = sK[r][d0], k1 = sK[r][d0 + 1], k2 = sK[r][d0 + 2], k3 = sK[r][d0 + 3];
            float v0 = sV[r][e0], v1 = sV[r][e0 + 1], v2 = sV[r][e0 + 2], v3 = sV[r][e0 + 3];
            acc[0][0] = fmaf(k0, v0, acc[0][0]); acc[0][1] = fmaf(k0, v1, acc[0][1]);
            acc[0][2] = fmaf(k0, v2, acc[0][2]); acc[0][3] = fmaf(k0, v3, acc[0][3]);
            acc[1][0] = fmaf(k1, v0, acc[1][0]); acc[1][1] = fmaf(k1, v1, acc[1][1]);
            acc[1][2] = fmaf(k1, v2, acc[1][2]); acc[1][3] = fmaf(k1, v3, acc[1][3]);
            acc[2][0] = fmaf(k2, v0, acc[2][0]); acc[2][1] = fmaf(k2, v1, acc[2][1]);
            acc[2][2] = fmaf(k2, v2, acc[2][2]); acc[2][3] = fmaf(k2, v3, acc[2][3]);
            acc[3][0] = fmaf(k3, v0, acc[3][0]); acc[3][1] = fmaf(k3, v1, acc[3][1]);
            acc[3][2] = fmaf(k3, v2, acc[3][2]); acc[3][3] = fmaf(k3, v3, acc[3][3]);
        }
        if (tid < 64) {
#pragma unroll
            for (int r = 0; r < 8; r++) ks += sK[r][tid];
        }
        __syncthreads();
    }

    float* kvp = g_KV + (size_t)bh * Dd * Dd;
#pragma unroll
    for (int i = 0; i < 4; i++)
#pragma unroll
        for (int j = 0; j < 4; j++)
            atomicAdd(&kvp[(d0 + i) * Dd + (e0 + j)], acc[i][j]);
    if (tid < 64) atomicAdd(&g_Ksum[bh * Dd + tid], ks);
}

__global__ __launch_bounds__(256) void y_kernel()
{
    const int bh = blockIdx.y;
    const int b = bh >> 3, h = bh & 7;
    const int t0 = blockIdx.x * 64;
    const int tid = threadIdx.x;

    __shared__ float sKV[64][64];
    __shared__ float sQ[64][65];
    __shared__ float sks[64];

    const float* kvp = g_KV + (size_t)bh * Dd * Dd;
#pragma unroll
    for (int i = 0; i < 16; i++) {
        int idx = tid + i * 256;
        sKV[idx >> 6][idx & 63] = kvp[idx];
    }
    if (tid < 64) sks[tid] = g_Ksum[bh * Dd + tid];
#pragma unroll
    for (int i = 0; i < 8; i++) {
        int idx = tid + i * 256;                 // 0..2047 half2 slots (64 rows x 32)
        int r = idx >> 5;
        int d2 = (idx & 31) * 2;
        float2 qf = __half22float2(*(const __half2*)(
            g_Qh + ((size_t)b * Tt + t0 + r) * Cc + h * Dd + d2));
        sQ[r][d2] = qf.x; sQ[r][d2 + 1] = qf.y;
    }
    __syncthreads();

    const int tok = tid >> 2;
    const int e0 = (tid & 3) * 16;

    float acc[16];
#pragma unroll
    for (int j = 0; j < 16; j++) acc[j] = 0.f;
    float nrm = 0.f;

#pragma unroll
    for (int d = 0; d < 64; d++) {
        float q = sQ[tok][d];
        nrm = fmaf(q, sks[d], nrm);
        const float4* kr = (const float4*)&sKV[d][e0];
        float4 c0 = kr[0], c1 = kr[1], c2 = kr[2], c3 = kr[3];
        acc[0]  = fmaf(q, c0.x, acc[0]);  acc[1]  = fmaf(q, c0.y, acc[1]);
        acc[2]  = fmaf(q, c0.z, acc[2]);  acc[3]  = fmaf(q, c0.w, acc[3]);
        acc[4]  = fmaf(q, c1.x, acc[4]);  acc[5]  = fmaf(q, c1.y, acc[5]);
        acc[6]  = fmaf(q, c1.z, acc[6]);  acc[7]  = fmaf(q, c1.w, acc[7]);
        acc[8]  = fmaf(q, c2.x, acc[8]);  acc[9]  = fmaf(q, c2.y, acc[9]);
        acc[10] = fmaf(q, c2.z, acc[10]); acc[11] = fmaf(q, c2.w, acc[11]);
        acc[12] = fmaf(q, c3.x, acc[12]); acc[13] = fmaf(q, c3.y, acc[13]);
        acc[14] = fmaf(q, c3.z, acc[14]); acc[15] = fmaf(q, c3.w, acc[15]);
    }

    float inv = 1.f / (nrm + 1e-6f);
    size_t ob = ((size_t)b * Tt + t0 + tok) * Cc + h * Dd + e0;
#pragma unroll
    for (int j = 0; j < 16; j += 2) {
        __half2 hv = __floats2half2_rn(acc[j] * inv, acc[j + 1] * inv);
        *(__half2*)(g_Yh + ob + j) = hv;
    }
}

// ---------------- launch ----------------
extern "C" void kernel_launch(void* const* d_in, const int* in_sizes, int n_in,
                              void* d_out, int out_size)
{
    const float* x  = (const float*)d_in[0];
    const float* Wq = (const float*)d_in[1];
    const float* bq = (const float*)d_in[2];
    const float* Wk = (const float*)d_in[3];
    const float* bk = (const float*)d_in[4];
    const float* Wv = (const float*)d_in[5];
    const float* bv = (const float*)d_in[6];
    const float* Wo = (const float*)d_in[7];
    const float* bo = (const float*)d_in[8];
    float* out = (float*)d_out;

    static __half *pXh = nullptr, *pWh, *pQh, *pKh, *pVh, *pYh;
    static bool inited = false;
    if (!inited) {
        cudaGetSymbolAddress((void**)&pXh, g_Xh);
        cudaGetSymbolAddress((void**)&pWh, g_Wh);
        cudaGetSymbolAddress((void**)&pQh, g_Qh);
        cudaGetSymbolAddress((void**)&pKh, g_Kh);
        cudaGetSymbolAddress((void**)&pVh, g_Vh);
        cudaGetSymbolAddress((void**)&pYh, g_Yh);
        cudaFuncSetAttribute(gemm_f16, cudaFuncAttributeMaxDynamicSharedMemorySize, GEMM_SMEM);
        inited = true;
    }

    // f32 -> f16 conversion of GEMM inputs
    const float* Ws[4] = {Wq, Wk, Wv, Wo};
    {
        int n8 = NN * Cc / 8;
        cvt_f16<<<n8 / 256, 256>>>((const float4*)x, (uint4*)pXh, n8);
        int w8 = Cc * Cc / 8;
        for (int i = 0; i < 4; i++)
            cvt_f16<<<w8 / 256, 256>>>((const float4*)Ws[i], (uint4*)(pWh + (size_t)i * Cc * Cc), w8);
    }

    dim3 gg(NN / BM, Cc / BN);   // (512, 4)

    gemm_f16<<<gg, NTHR, GEMM_SMEM>>>(pXh, pWh + 0 * (size_t)Cc * Cc, bq, pQh, 1, 1);
    gemm_f16<<<gg, NTHR, GEMM_SMEM>>>(pXh, pWh + 1 * (size_t)Cc * Cc, bk, pKh, 1, 1);
    gemm_f16<<<gg, NTHR, GEMM_SMEM>>>(pXh, pWh + 2 * (size_t)Cc * Cc, bv, pVh, 0, 1);

    zero_kv<<<(BH * Dd * Dd + 255) / 256, 256>>>();
    kv_accum<<<dim3(BH, KV_SPLIT), 256>>>();
    y_kernel<<<dim3(Tt / 64, BH), 256>>>();

    gemm_f16<<<gg, NTHR, GEMM_SMEM>>>(pYh, pWh + 3 * (size_t)Cc * Cc, bo, out, 0, 0);
}

// round 9
// speedup vs baseline: 1.1590x; 1.1296x over previous
#include <cuda_runtime.h>
#include <cuda_fp16.h>
#include <math.h>
#include <stdint.h>

// ---------------- Problem constants ----------------
#define Bb 8
#define Tt 8192
#define Cc 512
#define Hh 8
#define Dd 64
#define NN (Bb*Tt)         // 65536 tokens
#define BH (Bb*Hh)         // 64
#define KV_SPLIT 16

// ---------------- Scratch (device globals) ----------------
__device__ __half g_Xh[(size_t)NN*Cc];
__device__ __half g_Wh[(size_t)4*Cc*Cc];
__device__ __half g_Qh[(size_t)NN*Cc];
__device__ __half g_Kh[(size_t)NN*Cc];
__device__ __half g_Vh[(size_t)NN*Cc];
__device__ __half g_Yh[(size_t)NN*Cc];
__device__ float  g_KV[(size_t)BH*Dd*Dd];
__device__ float  g_Ksum[(size_t)BH*Dd];

// ---------------- helpers ----------------
__device__ __forceinline__ uint32_t smem_u32(const void* p) {
    uint32_t a;
    asm("{ .reg .u64 t; cvta.to.shared.u64 t, %1; cvt.u32.u64 %0, t; }" : "=r"(a) : "l"(p));
    return a;
}
#define CP_ASYNC16(dst, src) \
    asm volatile("cp.async.cg.shared.global [%0], [%1], 16;" :: "r"(dst), "l"(src) : "memory")
#define CP_COMMIT() asm volatile("cp.async.commit_group;" ::: "memory")
#define CP_WAIT(n)  asm volatile("cp.async.wait_group %0;" :: "n"(n) : "memory")

__device__ __forceinline__ void ldsm_x4(uint32_t* r, uint32_t addr) {
    asm volatile("ldmatrix.sync.aligned.m8n8.x4.shared.b16 {%0,%1,%2,%3}, [%4];"
                 : "=r"(r[0]), "=r"(r[1]), "=r"(r[2]), "=r"(r[3]) : "r"(addr));
}
__device__ __forceinline__ void mma_f16(float* c, const uint32_t* a, uint32_t b0, uint32_t b1) {
    asm volatile("mma.sync.aligned.m16n8k16.row.col.f32.f16.f16.f32 "
                 "{%0,%1,%2,%3},{%4,%5,%6,%7},{%8,%9},{%0,%1,%2,%3};"
                 : "+f"(c[0]), "+f"(c[1]), "+f"(c[2]), "+f"(c[3])
                 : "r"(a[0]), "r"(a[1]), "r"(a[2]), "r"(a[3]), "r"(b0), "r"(b1));
}

// ---------------- GEMM config (R6: fp16, 128x128 CTA, 8 warps of 64x32) ----------------
#define BM 128
#define BN 128
#define BKH 64                      // K halves per stage (128 B rows)
#define NKH (Cc / BKH)              // 8
#define ASTRH 72                    // padded row stride in halves
#define TILEH (BM * ASTRH)          // 9216 halves / operand
#define STAGEH (2 * TILEH)          // A + B
#define NSTG 3
#define GEMM_SMEM (NSTG * STAGEH * 2)   // 110592 bytes

// Core mainloop shared by both GEMM kernels. Computes acc for tile (m0, n0).
// A: tokens x Cc (fp16), B: rows of W (fp16).
__device__ __forceinline__ void gemm_core(
    const __half* __restrict__ A, const __half* __restrict__ B,
    int m0, int n0, __half* smh, float acc[4][4][4])
{
    const int tid = threadIdx.x;
    const int wid = tid >> 5;
    const int lane = tid & 31;
    const int m_warp = (wid >> 2) * 64;
    const int n_warp = (wid & 3) * 32;

    const int g8 = lane >> 3;
    const int r8 = lane & 7;
    const int a_row_l = r8 + (g8 & 1) * 8;
    const int a_kb    = (g8 >> 1) * 16;
    const int b_row_l = r8 + (g8 >> 1) * 8;
    const int b_kb    = (g8 & 1) * 16;

    const uint32_t smb = smem_u32(smh);

#pragma unroll
    for (int i = 0; i < 4; i++)
#pragma unroll
        for (int j = 0; j < 4; j++)
#pragma unroll
            for (int k = 0; k < 4; k++) acc[i][j][k] = 0.f;

    auto load_stage = [&](int kc, int s) {
        const __half* gA = A + (size_t)m0 * Cc + kc * BKH;
        const __half* gB = B + (size_t)n0 * Cc + kc * BKH;
        uint32_t dA = smb + (uint32_t)(s * STAGEH) * 2;
        uint32_t dB = dA + (uint32_t)TILEH * 2;
#pragma unroll
        for (int i = 0; i < 4; i++) {
            int idx = tid + i * 256;
            int row = idx >> 3;
            int c8 = idx & 7;
            CP_ASYNC16(dA + (uint32_t)(row * ASTRH + c8 * 8) * 2, gA + (size_t)row * Cc + c8 * 8);
        }
#pragma unroll
        for (int i = 0; i < 4; i++) {
            int idx = tid + i * 256;
            int row = idx >> 3;
            int c8 = idx & 7;
            CP_ASYNC16(dB + (uint32_t)(row * ASTRH + c8 * 8) * 2, gB + (size_t)row * Cc + c8 * 8);
        }
        CP_COMMIT();
    };

    load_stage(0, 0);
    load_stage(1, 1);

    for (int kt = 0; kt < NKH; kt++) {
        if (kt < NKH - 1) CP_WAIT(1); else CP_WAIT(0);
        __syncthreads();
        if (kt + 2 < NKH) load_stage(kt + 2, (kt + 2) % 3);

        const int s = kt % 3;
        const uint32_t aB = smb + (uint32_t)(s * STAGEH) * 2
                          + (uint32_t)((m_warp + a_row_l) * ASTRH) * 2 + a_kb;
        const uint32_t bB = smb + (uint32_t)(s * STAGEH + TILEH) * 2
                          + (uint32_t)((n_warp + b_row_l) * ASTRH) * 2 + b_kb;

#pragma unroll
        for (int ks = 0; ks < 4; ks++) {
            uint32_t af[4][4];
#pragma unroll
            for (int mi = 0; mi < 4; mi++)
                ldsm_x4(af[mi], aB + (uint32_t)(mi * 16 * ASTRH) * 2 + ks * 32);
            uint32_t bf[2][4];
#pragma unroll
            for (int p = 0; p < 2; p++)
                ldsm_x4(bf[p], bB + (uint32_t)(p * 16 * ASTRH) * 2 + ks * 32);
#pragma unroll
            for (int mi = 0; mi < 4; mi++) {
#pragma unroll
                for (int p = 0; p < 2; p++) {
                    mma_f16(acc[mi][p * 2 + 0], af[mi], bf[p][0], bf[p][1]);
                    mma_f16(acc[mi][p * 2 + 1], af[mi], bf[p][2], bf[p][3]);
                }
            }
        }
    }
}

// Fused QKV projection: grid (NN/BM, 12). Segment = by>>2: 0=Q,1=K,2=V.
__global__ __launch_bounds__(256, 2)
void gemm_qkv(const __half* __restrict__ X, const __half* __restrict__ W,
              const float* __restrict__ bq, const float* __restrict__ bk,
              const float* __restrict__ bv,
              __half* __restrict__ Q, __half* __restrict__ K, __half* __restrict__ V)
{
    extern __shared__ __half smh[];
    const int seg = blockIdx.y >> 2;
    const int n0 = (blockIdx.y & 3) * BN;
    const int m0 = blockIdx.x * BM;

    const __half* B = W + (size_t)seg * Cc * Cc;
    const float* bias = (seg == 0) ? bq : (seg == 1) ? bk : bv;
    __half* outp = (seg == 0) ? Q : (seg == 1) ? K : V;
    const int act = (seg < 2);

    float acc[4][4][4];
    gemm_core(X, B, m0, n0, smh, acc);

    const int tid = threadIdx.x;
    const int wid = tid >> 5;
    const int lane = tid & 31;
    const int m_warp = (wid >> 2) * 64;
    const int n_warp = (wid & 3) * 32;
    const int r_lo = lane >> 2;
    const int c_off = (lane & 3) * 2;
#pragma unroll
    for (int mi = 0; mi < 4; mi++) {
#pragma unroll
        for (int nj = 0; nj < 4; nj++) {
            int col = n0 + n_warp + nj * 8 + c_off;
            float b0 = bias[col], b1 = bias[col + 1];
#pragma unroll
            for (int half_ = 0; half_ < 2; half_++) {
                int row = m0 + m_warp + mi * 16 + r_lo + half_ * 8;
                float v0 = acc[mi][nj][half_ * 2 + 0] + b0;
                float v1 = acc[mi][nj][half_ * 2 + 1] + b1;
                if (act) {
                    v0 = (v0 > 0.f) ? v0 + 1.f : expf(v0);
                    v1 = (v1 > 0.f) ? v1 + 1.f : expf(v1);
                }
                __half2 hv = __floats2half2_rn(v0, v1);
                *(__half2*)(outp + (size_t)row * Cc + col) = hv;
            }
        }
    }
}

// Output projection: f32 store, no activation.
__global__ __launch_bounds__(256, 2)
void gemm_out(const __half* __restrict__ Y, const __half* __restrict__ W,
              const float* __restrict__ bias, float* __restrict__ outp)
{
    extern __shared__ __half smh[];
    const int m0 = blockIdx.x * BM;
    const int n0 = blockIdx.y * BN;

    float acc[4][4][4];
    gemm_core(Y, W, m0, n0, smh, acc);

    const int tid = threadIdx.x;
    const int wid = tid >> 5;
    const int lane = tid & 31;
    const int m_warp = (wid >> 2) * 64;
    const int n_warp = (wid & 3) * 32;
    const int r_lo = lane >> 2;
    const int c_off = (lane & 3) * 2;
#pragma unroll
    for (int mi = 0; mi < 4; mi++) {
#pragma unroll
        for (int nj = 0; nj < 4; nj++) {
            int col = n0 + n_warp + nj * 8 + c_off;
            float b0 = bias[col], b1 = bias[col + 1];
#pragma unroll
            for (int half_ = 0; half_ < 2; half_++) {
                int row = m0 + m_warp + mi * 16 + r_lo + half_ * 8;
                float v0 = acc[mi][nj][half_ * 2 + 0] + b0;
                float v1 = acc[mi][nj][half_ * 2 + 1] + b1;
                *(float2*)(outp + (size_t)row * Cc + col) = make_float2(v0, v1);
            }
        }
    }
}

// ---------------- f32 -> f16 conversions ----------------
__global__ __launch_bounds__(256) void cvt_f16(const float4* __restrict__ src,
                                               uint4* __restrict__ dst, int n8)
{
    int i = blockIdx.x * blockDim.x + threadIdx.x;
    if (i < n8) {
        float4 a = src[2 * i], b = src[2 * i + 1];
        __half2 h0 = __floats2half2_rn(a.x, a.y);
        __half2 h1 = __floats2half2_rn(a.z, a.w);
        __half2 h2 = __floats2half2_rn(b.x, b.y);
        __half2 h3 = __floats2half2_rn(b.z, b.w);
        uint4 o;
        o.x = *(uint32_t*)&h0; o.y = *(uint32_t*)&h1;
        o.z = *(uint32_t*)&h2; o.w = *(uint32_t*)&h3;
        dst[i] = o;
    }
}

// All four weight matrices in one launch. w8 = Cc*Cc/8 units per matrix.
__global__ __launch_bounds__(256) void cvt_w(
    const float4* __restrict__ w0, const float4* __restrict__ w1,
    const float4* __restrict__ w2, const float4* __restrict__ w3,
    uint4* __restrict__ dst)
{
    const int w8 = Cc * Cc / 8;
    int i = blockIdx.x * blockDim.x + threadIdx.x;
    if (i >= 4 * w8) return;
    int seg = i / w8, j = i - seg * w8;
    const float4* src = (seg == 0) ? w0 : (seg == 1) ? w1 : (seg == 2) ? w2 : w3;
    float4 a = src[2 * j], b = src[2 * j + 1];
    __half2 h0 = __floats2half2_rn(a.x, a.y);
    __half2 h1 = __floats2half2_rn(a.z, a.w);
    __half2 h2 = __floats2half2_rn(b.x, b.y);
    __half2 h3 = __floats2half2_rn(b.z, b.w);
    uint4 o;
    o.x = *(uint32_t*)&h0; o.y = *(uint32_t*)&h1;
    o.z = *(uint32_t*)&h2; o.w = *(uint32_t*)&h3;
    dst[i] = o;
}

// ---------------- attention-side kernels ----------------
__global__ void zero_kv()
{
    int i = blockIdx.x * blockDim.x + threadIdx.x;
    if (i < BH * Dd * Dd) g_KV[i] = 0.f;
    if (i < BH * Dd)      g_Ksum[i] = 0.f;
}

#define RCH 16   // rows per chunk
__global__ __launch_bounds__(256) void kv_accum()
{
    const int bh = blockIdx.x;
    const int b = bh >> 3, h = bh & 7;
    const int tid = threadIdx.x;
    const int rows = Tt / KV_SPLIT;          // 512
    const size_t base = ((size_t)b * Tt + (size_t)blockIdx.y * rows) * Cc + h * Dd;

    __shared__ float sK[RCH][64];
    __shared__ float sV[RCH][64];

    const int d0 = (tid >> 4) * 4;
    const int e0 = (tid & 15) * 4;

    float acc[4][4];
#pragma unroll
    for (int i = 0; i < 4; i++)
#pragma unroll
        for (int j = 0; j < 4; j++) acc[i][j] = 0.f;
    float ks = 0.f;

    for (int r0 = 0; r0 < rows; r0 += RCH) {
#pragma unroll
        for (int i = 0; i < RCH * 32 / 256; i++) {   // 2 half2 per thread
            int lin = tid + i * 256;
            int rr = lin >> 5;                       // 0..15
            int pp = (lin & 31) * 2;
            size_t g = base + (size_t)(r0 + rr) * Cc + pp;
            float2 kf = __half22float2(*(const __half2*)(g_Kh + g));
            float2 vf = __half22float2(*(const __half2*)(g_Vh + g));
            sK[rr][pp] = kf.x; sK[rr][pp + 1] = kf.y;
            sV[rr][pp] = vf.x; sV[rr][pp + 1] = vf.y;
        }
        __syncthreads();
#pragma unroll
        for (int r = 0; r < RCH; r++) {
            float k0 = sK[r][d0], k1 = sK[r][d0 + 1], k2 = sK[r][d0 + 2], k3 = sK[r][d0 + 3];
            float v0 = sV[r][e0], v1 = sV[r][e0 + 1], v2 = sV[r][e0 + 2], v3 = sV[r][e0 + 3];
            acc[0][0] = fmaf(k0, v0, acc[0][0]); acc[0][1] = fmaf(k0, v1, acc[0][1]);
            acc[0][2] = fmaf(k0, v2, acc[0][2]); acc[0][3] = fmaf(k0, v3, acc[0][3]);
            acc[1][0] = fmaf(k1, v0, acc[1][0]); acc[1][1] = fmaf(k1, v1, acc[1][1]);
            acc[1][2] = fmaf(k1, v2, acc[1][2]); acc[1][3] = fmaf(k1, v3, acc[1][3]);
            acc[2][0] = fmaf(k2, v0, acc[2][0]); acc[2][1] = fmaf(k2, v1, acc[2][1]);
            acc[2][2] = fmaf(k2, v2, acc[2][2]); acc[2][3] = fmaf(k2, v3, acc[2][3]);
            acc[3][0] = fmaf(k3, v0, acc[3][0]); acc[3][1] = fmaf(k3, v1, acc[3][1]);
            acc[3][2] = fmaf(k3, v2, acc[3][2]); acc[3][3] = fmaf(k3, v3, acc[3][3]);
        }
        if (tid < 64) {
#pragma unroll
            for (int r = 0; r < RCH; r++) ks += sK[r][tid];
        }
        __syncthreads();
    }

    float* kvp = g_KV + (size_t)bh * Dd * Dd;
#pragma unroll
    for (int i = 0; i < 4; i++)
#pragma unroll
        for (int j = 0; j < 4; j++)
            atomicAdd(&kvp[(d0 + i) * Dd + (e0 + j)], acc[i][j]);
    if (tid < 64) atomicAdd(&g_Ksum[bh * Dd + tid], ks);
}

__global__ __launch_bounds__(256) void y_kernel()
{
    const int bh = blockIdx.y;
    const int b = bh >> 3, h = bh & 7;
    const int t0 = blockIdx.x * 64;
    const int tid = threadIdx.x;

    __shared__ float sKV[64][64];
    __shared__ float sQ[64][65];
    __shared__ float sks[64];

    const float* kvp = g_KV + (size_t)bh * Dd * Dd;
#pragma unroll
    for (int i = 0; i < 16; i++) {
        int idx = tid + i * 256;
        sKV[idx >> 6][idx & 63] = kvp[idx];
    }
    if (tid < 64) sks[tid] = g_Ksum[bh * Dd + tid];
#pragma unroll
    for (int i = 0; i < 8; i++) {
        int idx = tid + i * 256;
        int r = idx >> 5;
        int d2 = (idx & 31) * 2;
        float2 qf = __half22float2(*(const __half2*)(
            g_Qh + ((size_t)b * Tt + t0 + r) * Cc + h * Dd + d2));
        sQ[r][d2] = qf.x; sQ[r][d2 + 1] = qf.y;
    }
    __syncthreads();

    const int tok = tid >> 2;
    const int e0 = (tid & 3) * 16;

    float acc[16];
#pragma unroll
    for (int j = 0; j < 16; j++) acc[j] = 0.f;
    float nrm = 0.f;

#pragma unroll
    for (int d = 0; d < 64; d++) {
        float q = sQ[tok][d];
        nrm = fmaf(q, sks[d], nrm);
        const float4* kr = (const float4*)&sKV[d][e0];
        float4 c0 = kr[0], c1 = kr[1], c2 = kr[2], c3 = kr[3];
        acc[0]  = fmaf(q, c0.x, acc[0]);  acc[1]  = fmaf(q, c0.y, acc[1]);
        acc[2]  = fmaf(q, c0.z, acc[2]);  acc[3]  = fmaf(q, c0.w, acc[3]);
        acc[4]  = fmaf(q, c1.x, acc[4]);  acc[5]  = fmaf(q, c1.y, acc[5]);
        acc[6]  = fmaf(q, c1.z, acc[6]);  acc[7]  = fmaf(q, c1.w, acc[7]);
        acc[8]  = fmaf(q, c2.x, acc[8]);  acc[9]  = fmaf(q, c2.y, acc[9]);
        acc[10] = fmaf(q, c2.z, acc[10]); acc[11] = fmaf(q, c2.w, acc[11]);
        acc[12] = fmaf(q, c3.x, acc[12]); acc[13] = fmaf(q, c3.y, acc[13]);
        acc[14] = fmaf(q, c3.z, acc[14]); acc[15] = fmaf(q, c3.w, acc[15]);
    }

    float inv = 1.f / (nrm + 1e-6f);
    size_t ob = ((size_t)b * Tt + t0 + tok) * Cc + h * Dd + e0;
#pragma unroll
    for (int j = 0; j < 16; j += 2) {
        __half2 hv = __floats2half2_rn(acc[j] * inv, acc[j + 1] * inv);
        *(__half2*)(g_Yh + ob + j) = hv;
    }
}

// ---------------- launch ----------------
extern "C" void kernel_launch(void* const* d_in, const int* in_sizes, int n_in,
                              void* d_out, int out_size)
{
    const float* x  = (const float*)d_in[0];
    const float* Wq = (const float*)d_in[1];
    const float* bq = (const float*)d_in[2];
    const float* Wk = (const float*)d_in[3];
    const float* bk = (const float*)d_in[4];
    const float* Wv = (const float*)d_in[5];
    const float* bv = (const float*)d_in[6];
    const float* Wo = (const float*)d_in[7];
    const float* bo = (const float*)d_in[8];
    float* out = (float*)d_out;

    static __half *pXh = nullptr, *pWh, *pQh, *pKh, *pVh, *pYh;
    static bool inited = false;
    if (!inited) {
        cudaGetSymbolAddress((void**)&pXh, g_Xh);
        cudaGetSymbolAddress((void**)&pWh, g_Wh);
        cudaGetSymbolAddress((void**)&pQh, g_Qh);
        cudaGetSymbolAddress((void**)&pKh, g_Kh);
        cudaGetSymbolAddress((void**)&pVh, g_Vh);
        cudaGetSymbolAddress((void**)&pYh, g_Yh);
        cudaFuncSetAttribute(gemm_qkv, cudaFuncAttributeMaxDynamicSharedMemorySize, GEMM_SMEM);
        cudaFuncSetAttribute(gemm_out, cudaFuncAttributeMaxDynamicSharedMemorySize, GEMM_SMEM);
        inited = true;
    }

    // f32 -> f16 conversion of GEMM inputs
    {
        int n8 = NN * Cc / 8;
        cvt_f16<<<n8 / 256, 256>>>((const float4*)x, (uint4*)pXh, n8);
        int tot = 4 * Cc * Cc / 8;
        cvt_w<<<(tot + 255) / 256, 256>>>((const float4*)Wq, (const float4*)Wk,
                                          (const float4*)Wv, (const float4*)Wo, (uint4*)pWh);
    }

    // Fused Q/K/V projections: one launch, grid (512, 12)
    gemm_qkv<<<dim3(NN / BM, 12), 256, GEMM_SMEM>>>(pXh, pWh, bq, bk, bv, pQh, pKh, pVh);

    zero_kv<<<(BH * Dd * Dd + 255) / 256, 256>>>();
    kv_accum<<<dim3(BH, KV_SPLIT), 256>>>();
    y_kernel<<<dim3(Tt / 64, BH), 256>>>();

    gemm_out<<<dim3(NN / BM, Cc / BN), 256, GEMM_SMEM>>>(pYh, pWh + 3 * (size_t)Cc * Cc, bo, out);
}